// round 10
// baseline (speedup 1.0000x reference)
#include <cuda_runtime.h>
#include <cstdint>

#define S 128
#define C 32
#define NN 4096
#define T 512

extern __shared__ char dyn_smem[];

// ---------------- scratch ----------------
__device__ __align__(256) float g_P[S * NN];        // exp(log_softmax(emission)) [S,N]
__device__ __align__(256) float g_wexp[T * C];      // exp(log_softmax(weights))
__device__ __align__(256) float g_pR[T * C * S];    // p_t, tf32-rounded [T*C, S]
__device__ __align__(256) float g_PTR[NN * S];      // P^T tf32-rounded [n, s]
__device__ __align__(256) float g_Tpow[512 * S * S];// T^t table (t*16384), tf32-rounded

// ---------------- helpers ----------------
__device__ __forceinline__ uint32_t smem_u32(const void* p) {
    uint32_t a;
    asm("{ .reg .u64 t; cvta.to.shared.u64 t, %1; cvt.u32.u64 %0, t; }" : "=r"(a) : "l"(p));
    return a;
}
__device__ __forceinline__ void cp_async16(uint32_t dst, const void* src) {
    asm volatile("cp.async.cg.shared.global [%0], [%1], 16;" :: "r"(dst), "l"(src));
}
#define CP_COMMIT() asm volatile("cp.async.commit_group;" ::: "memory")
#define CP_WAIT(n)  asm volatile("cp.async.wait_group %0;" :: "n"(n) : "memory")

__device__ __forceinline__ float to_tf32(float x) {
    uint32_t u;
    asm("cvt.rna.tf32.f32 %0, %1;" : "=r"(u) : "f"(x));
    return __uint_as_float(u);
}
__device__ __forceinline__ void mma_tf32(float* d, const uint32_t* a, const uint32_t* b) {
    asm volatile(
        "mma.sync.aligned.m16n8k8.row.col.f32.tf32.tf32.f32 "
        "{%0,%1,%2,%3},{%4,%5,%6,%7},{%8,%9},{%0,%1,%2,%3};"
        : "+f"(d[0]), "+f"(d[1]), "+f"(d[2]), "+f"(d[3])
        : "r"(a[0]), "r"(a[1]), "r"(a[2]), "r"(a[3]), "r"(b[0]), "r"(b[1]));
}
__device__ __forceinline__ float warpRedMax(float v) {
#pragma unroll
    for (int o = 16; o > 0; o >>= 1) v = fmaxf(v, __shfl_xor_sync(0xffffffffu, v, o));
    return v;
}
__device__ __forceinline__ float warpRedSum(float v) {
#pragma unroll
    for (int o = 16; o > 0; o >>= 1) v += __shfl_xor_sync(0xffffffffu, v, o);
    return v;
}

// ---------------- fused log_softmax over all 4 inputs ----------------
// blocks [0,128): emission -> o4 + g_P
// blocks [128,640): weights -> o5 + g_wexp
// blocks [640,672): init -> o3 (t=0) + g_pR (rounded)
// blocks [672,800): trans -> g_Tpow[1] (rounded)
__global__ void softmax_all(const float* __restrict__ init, const float* __restrict__ weights,
                            const float* __restrict__ emis, const float* __restrict__ trans,
                            float* __restrict__ o3, float* __restrict__ o4, float* __restrict__ o5) {
    int b = blockIdx.x;
    const float* src;
    float* dlog = nullptr;
    float* dexp;
    bool rnd = false;
    int ncols;
    if (b < 128) {
        int row = b;
        src = emis + (size_t)row * NN;  ncols = NN;
        dlog = o4 + (size_t)row * NN;   dexp = g_P + (size_t)row * NN;
    } else if (b < 640) {
        int row = b - 128;
        src = weights + (size_t)row * C;  ncols = C;
        dlog = o5 + (size_t)row * C;      dexp = g_wexp + (size_t)row * C;
    } else if (b < 672) {
        int row = b - 640;
        src = init + (size_t)row * S;  ncols = S;
        dlog = o3 + (size_t)row * S;   dexp = g_pR + (size_t)row * S;
        rnd = true;
    } else {
        int row = b - 672;
        src = trans + (size_t)row * S;  ncols = S;
        dexp = g_Tpow + (size_t)S * S + (size_t)row * S;   // T^1
        rnd = true;
    }

    int tid = threadIdx.x, lane = tid & 31, wid = tid >> 5;
    __shared__ float red[8];

    float m = -3.4e38f;
    for (int i = tid; i < ncols; i += blockDim.x) m = fmaxf(m, src[i]);
    m = warpRedMax(m);
    if (lane == 0) red[wid] = m;
    __syncthreads();
    if (wid == 0) {
        float v = (lane < 8) ? red[lane] : -3.4e38f;
        v = warpRedMax(v);
        if (lane == 0) red[0] = v;
    }
    __syncthreads();
    m = red[0];
    __syncthreads();

    float s = 0.f;
    for (int i = tid; i < ncols; i += blockDim.x) s += __expf(src[i] - m);
    s = warpRedSum(s);
    if (lane == 0) red[wid] = s;
    __syncthreads();
    if (wid == 0) {
        float v = (lane < 8) ? red[lane] : 0.f;
        v = warpRedSum(v);
        if (lane == 0) red[0] = v;
    }
    __syncthreads();
    float lse = m + __logf(red[0]);

    for (int i = tid; i < ncols; i += blockDim.x) {
        float v = src[i] - lse;
        if (dlog) dlog[i] = v;
        float e = __expf(v);
        dexp[i] = rnd ? to_tf32(e) : e;
    }
}

// ---------------- radix-4 power level ----------------
// Have T^1..T^L. Block b computes t = L+1+b: m = (t-1)/L chained GEMMs:
// X = T^j; repeat m: X = T^L * X. Stores tf32-rounded.
static constexpr int PW = 136;                     // padded words per 128-row
static constexpr int MAT_W = 128 * PW;
static constexpr int POW_SMEM = 3 * MAT_W * 4;     // 208896

__global__ __launch_bounds__(256, 1) void power_level(int L) {
    float* sm0 = reinterpret_cast<float*>(dyn_smem);
    float* Ms = sm0;
    float* Xs = sm0 + MAT_W;
    float* Ys = sm0 + 2 * MAT_W;
    int tid = threadIdx.x, lane = tid & 31, wid = tid >> 5;
    int t = L + 1 + (int)blockIdx.x;
    int m = (t - 1) / L;
    int j = t - m * L;

    const float4* gM = reinterpret_cast<const float4*>(g_Tpow + (size_t)L * 16384);
    const float4* gX = reinterpret_cast<const float4*>(g_Tpow + (size_t)j * 16384);
    for (int i = tid; i < 4096; i += 256) {
        int row = i >> 5, c = i & 31;
        *reinterpret_cast<float4*>(Ms + row * PW + c * 4) = gM[i];
        *reinterpret_cast<float4*>(Xs + row * PW + c * 4) = gX[i];
    }
    __syncthreads();

    int wrow = wid * 16;
    for (int it = 0; it < m; it++) {
        float acc[16][4];
#pragma unroll
        for (int nt = 0; nt < 16; nt++)
#pragma unroll
            for (int e = 0; e < 4; e++) acc[nt][e] = 0.f;

#pragma unroll
        for (int kt = 0; kt < 16; kt++) {
            int r = wrow + (lane >> 2), k = kt * 8 + (lane & 3);
            uint32_t a[4];
            a[0] = __float_as_uint(Ms[r * PW + k]);
            a[1] = __float_as_uint(Ms[(r + 8) * PW + k]);
            a[2] = __float_as_uint(Ms[r * PW + k + 4]);
            a[3] = __float_as_uint(Ms[(r + 8) * PW + k + 4]);
#pragma unroll
            for (int nt = 0; nt < 16; nt++) {
                int n = nt * 8 + (lane >> 2);
                uint32_t bf[2];
                bf[0] = __float_as_uint(Xs[k * PW + n]);
                bf[1] = __float_as_uint(Xs[(k + 4) * PW + n]);
                mma_tf32(acc[nt], a, bf);
            }
        }
        int r = wrow + (lane >> 2), c2 = (lane & 3) * 2;
#pragma unroll
        for (int nt = 0; nt < 16; nt++) {
            Ys[r * PW + nt * 8 + c2]           = to_tf32(acc[nt][0]);
            Ys[r * PW + nt * 8 + c2 + 1]       = to_tf32(acc[nt][1]);
            Ys[(r + 8) * PW + nt * 8 + c2]     = to_tf32(acc[nt][2]);
            Ys[(r + 8) * PW + nt * 8 + c2 + 1] = to_tf32(acc[nt][3]);
        }
        __syncthreads();
        float* tmp = Xs; Xs = Ys; Ys = tmp;
    }

    float4* gT = reinterpret_cast<float4*>(g_Tpow + (size_t)t * 16384);
    for (int i = tid; i < 4096; i += 256) {
        int row = i >> 5, c = i & 31;
        gT[i] = *reinterpret_cast<float4*>(Xs + row * PW + c * 4);
    }
}

// ---------------- apply: p_t = p_0 * T^t, fused o3=log(p) + g_pR ----------------
static constexpr int APPLY_SMEM = (32 + 128) * PW * 4;   // 87040

__global__ __launch_bounds__(256, 2) void apply_powers(float* __restrict__ o3) {
    float* P0s = reinterpret_cast<float*>(dyn_smem);    // 32 rows
    float* Ts = P0s + 32 * PW;                          // 128 rows
    int tid = threadIdx.x, lane = tid & 31, wid = tid >> 5;
    int t = 1 + (int)blockIdx.x;

    const float4* gp = reinterpret_cast<const float4*>(g_pR);   // t=0 block (rounded)
    for (int i = tid; i < 1024; i += 256) {
        int row = i >> 5, c = i & 31;
        *reinterpret_cast<float4*>(P0s + row * PW + c * 4) = gp[i];
    }
    const float4* gT = reinterpret_cast<const float4*>(g_Tpow + (size_t)t * 16384);
    for (int i = tid; i < 4096; i += 256) {
        int row = i >> 5, c = i & 31;
        *reinterpret_cast<float4*>(Ts + row * PW + c * 4) = gT[i];
    }
    __syncthreads();

    int wm = wid & 1, wn = wid >> 1;   // rows 16*wm, cols 32*wn
    float acc[4][4];
#pragma unroll
    for (int nt = 0; nt < 4; nt++)
#pragma unroll
        for (int e = 0; e < 4; e++) acc[nt][e] = 0.f;

#pragma unroll
    for (int kt = 0; kt < 16; kt++) {
        int r = wm * 16 + (lane >> 2), k = kt * 8 + (lane & 3);
        uint32_t a[4];
        a[0] = __float_as_uint(P0s[r * PW + k]);
        a[1] = __float_as_uint(P0s[(r + 8) * PW + k]);
        a[2] = __float_as_uint(P0s[r * PW + k + 4]);
        a[3] = __float_as_uint(P0s[(r + 8) * PW + k + 4]);
#pragma unroll
        for (int nt = 0; nt < 4; nt++) {
            int n = wn * 32 + nt * 8 + (lane >> 2);
            uint32_t bf[2];
            bf[0] = __float_as_uint(Ts[k * PW + n]);
            bf[1] = __float_as_uint(Ts[(k + 4) * PW + n]);
            mma_tf32(acc[nt], a, bf);
        }
    }

    size_t base = (size_t)t * (C * S);
    int r = wm * 16 + (lane >> 2), c2 = (lane & 3) * 2;
#pragma unroll
    for (int nt = 0; nt < 4; nt++) {
        int col = wn * 32 + nt * 8 + c2;
        g_pR[base + r * S + col]           = to_tf32(acc[nt][0]);
        g_pR[base + r * S + col + 1]       = to_tf32(acc[nt][1]);
        g_pR[base + (r + 8) * S + col]     = to_tf32(acc[nt][2]);
        g_pR[base + (r + 8) * S + col + 1] = to_tf32(acc[nt][3]);
        o3[base + r * S + col]           = __logf(acc[nt][0]);
        o3[base + r * S + col + 1]       = __logf(acc[nt][1]);
        o3[base + (r + 8) * S + col]     = __logf(acc[nt][2]);
        o3[base + (r + 8) * S + col + 1] = __logf(acc[nt][3]);
    }
}

// ---------------- transpose P [S,N] -> PTR tf32-rounded [N,S] ----------------
__global__ void transpose_P() {
    __shared__ float ts[32][33];
    int n0 = blockIdx.x * 32, s0 = blockIdx.y * 32;
    int tx = threadIdx.x, ty = threadIdx.y;   // (32, 8)
#pragma unroll
    for (int r = 0; r < 4; r++)
        ts[ty + r * 8][tx] = g_P[(size_t)(s0 + ty + r * 8) * NN + n0 + tx];
    __syncthreads();
#pragma unroll
    for (int r = 0; r < 4; r++) {
        int nloc = ty + r * 8;
        g_PTR[(size_t)(n0 + nloc) * S + s0 + tx] = to_tf32(ts[tx][nloc]);
    }
}

// ---------------- persistent tf32 GEMM + log epilogue (round 9, proven) ----
static constexpr int A_PW = 132;
static constexpr int A_BYTES = 128 * A_PW * 4;     // 67584
static constexpr int B_PW = 68;
static constexpr int B_CHUNK = 128 * B_PW * 4;     // 34816
static constexpr int MMA_SMEM = A_BYTES + 3 * B_CHUNK;  // 172032

__global__ __launch_bounds__(256, 1)
void mma_kernel(float* __restrict__ o1, float* __restrict__ o2) {
    char* sm = dyn_smem;
    uint32_t smb = smem_u32(sm);
    int tid = threadIdx.x, lane = tid & 31, wid = tid >> 5;
    int quad = blockIdx.x;

    const uint4* srcA = reinterpret_cast<const uint4*>(g_pR) + (size_t)quad * 128 * 32;
#pragma unroll
    for (int j = 0; j < 16; j++) {
        int i = tid + j * 256;
        int row = i >> 5, c = i & 31;
        cp_async16(smb + row * (A_PW * 4) + c * 16, srcA + row * 32 + c);
    }
    CP_COMMIT();

    auto issueB = [&](int chunk) {
        int tile = chunk >> 1, half = chunk & 1;
        const uint4* srcB = reinterpret_cast<const uint4*>(g_PTR)
                            + (size_t)tile * 128 * 32 + half * 16;
        uint32_t base = smb + A_BYTES + (chunk % 3) * B_CHUNK;
#pragma unroll
        for (int j = 0; j < 8; j++) {
            int i = tid + j * 256;
            int row = i >> 4, c = i & 15;
            cp_async16(base + row * (B_PW * 4) + c * 16, srcB + row * 32 + c);
        }
    };
    issueB(0); CP_COMMIT();
    issueB(1); CP_COMMIT();
    issueB(2); CP_COMMIT();

    int mrow = (wid & 3) * 32 + (lane >> 2);
    int nrowBase = (wid >> 2) * 64 + (lane >> 2);
    int kt = lane & 3;
    int t = quad * 4 + (wid & 3);
    int r0 = lane >> 2, cq = lane & 3;
    float wlane = g_wexp[t * C + lane];
    float wr0  = __shfl_sync(0xffffffffu, wlane, r0);
    float wr0b = __shfl_sync(0xffffffffu, wlane, r0 + 8);
    float wr1  = __shfl_sync(0xffffffffu, wlane, 16 + r0);
    float wr1b = __shfl_sync(0xffffffffu, wlane, 16 + r0 + 8);

    const uint32_t* As = reinterpret_cast<const uint32_t*>(sm);
    float acc[2][8][4];

    for (int chunk = 0; chunk < 64; chunk++) {
        int tile = chunk >> 1, half = chunk & 1;
        CP_WAIT(2);
        __syncthreads();
        const uint32_t* Bs =
            reinterpret_cast<const uint32_t*>(sm + A_BYTES + (chunk % 3) * B_CHUNK);

        if (half == 0) {
#pragma unroll
            for (int mt = 0; mt < 2; mt++)
#pragma unroll
                for (int nt = 0; nt < 8; nt++)
#pragma unroll
                    for (int e = 0; e < 4; e++) acc[mt][nt][e] = 0.f;
        }

#pragma unroll
        for (int step = 0; step < 8; step++) {
            int k0 = half * 64 + step * 8 + kt;
            uint32_t a[2][4];
#pragma unroll
            for (int mt = 0; mt < 2; mt++) {
                int r = mrow + mt * 16;
                a[mt][0] = As[r * A_PW + k0];
                a[mt][1] = As[(r + 8) * A_PW + k0];
                a[mt][2] = As[r * A_PW + k0 + 4];
                a[mt][3] = As[(r + 8) * A_PW + k0 + 4];
            }
#pragma unroll
            for (int nt = 0; nt < 8; nt++) {
                int n = nrowBase + nt * 8;
                uint32_t bf[2];
                bf[0] = Bs[n * B_PW + step * 8 + kt];
                bf[1] = Bs[n * B_PW + step * 8 + kt + 4];
#pragma unroll
                for (int mt = 0; mt < 2; mt++) mma_tf32(acc[mt][nt], a[mt], bf);
            }
        }
        __syncthreads();
        if (chunk + 3 < 64) issueB(chunk + 3);
        CP_COMMIT();

        if (half == 1) {
            int nb = tile * 128;
            int nbL = (wid >> 2) * 64;
#pragma unroll
            for (int nt = 0; nt < 8; nt++) {
                int ncol = nb + nbL + nt * 8 + cq * 2;
                float v0, v1;
                {
                    float2 s0 = make_float2(__logf(acc[0][nt][0]), __logf(acc[0][nt][1]));
                    float2 s1 = make_float2(__logf(acc[0][nt][2]), __logf(acc[0][nt][3]));
                    *reinterpret_cast<float2*>(&o2[((size_t)(t * C + r0)) * NN + ncol]) = s0;
                    *reinterpret_cast<float2*>(&o2[((size_t)(t * C + r0 + 8)) * NN + ncol]) = s1;
                    v0 = acc[0][nt][0] * wr0 + acc[0][nt][2] * wr0b;
                    v1 = acc[0][nt][1] * wr0 + acc[0][nt][3] * wr0b;
                }
                {
                    float2 s0 = make_float2(__logf(acc[1][nt][0]), __logf(acc[1][nt][1]));
                    float2 s1 = make_float2(__logf(acc[1][nt][2]), __logf(acc[1][nt][3]));
                    *reinterpret_cast<float2*>(&o2[((size_t)(t * C + 16 + r0)) * NN + ncol]) = s0;
                    *reinterpret_cast<float2*>(&o2[((size_t)(t * C + 24 + r0)) * NN + ncol]) = s1;
                    v0 += acc[1][nt][0] * wr1 + acc[1][nt][2] * wr1b;
                    v1 += acc[1][nt][1] * wr1 + acc[1][nt][3] * wr1b;
                }
#pragma unroll
                for (int o = 4; o < 32; o <<= 1) {
                    v0 += __shfl_xor_sync(0xffffffffu, v0, o);
                    v1 += __shfl_xor_sync(0xffffffffu, v1, o);
                }
                if (lane < 4) {
                    int n = nb + nbL + nt * 8 + lane * 2;
                    *reinterpret_cast<float2*>(&o1[(size_t)t * NN + n]) =
                        make_float2(__logf(v0), __logf(v1));
                }
            }
        }
    }
}

// ---------------- launch ----------------
extern "C" void kernel_launch(void* const* d_in, const int* in_sizes, int n_in,
                              void* d_out, int out_size) {
    (void)in_sizes; (void)n_in; (void)out_size;
    const float* init    = (const float*)d_in[0];   // [32,128]
    const float* weights = (const float*)d_in[1];   // [512,32]
    const float* emis    = (const float*)d_in[2];   // [128,4096]
    const float* trans   = (const float*)d_in[3];   // [128,128]

    float* out = (float*)d_out;
    float* o1 = out;                       // [512,4096]
    float* o2 = o1 + (size_t)T * NN;       // [512,32,4096]
    float* o3 = o2 + (size_t)T * C * NN;   // [512,32,128]
    float* o4 = o3 + (size_t)T * C * S;    // [128,4096]
    float* o5 = o4 + (size_t)S * NN;       // [512,32]

    cudaFuncSetAttribute(power_level, cudaFuncAttributeMaxDynamicSharedMemorySize, POW_SMEM);
    cudaFuncSetAttribute(apply_powers, cudaFuncAttributeMaxDynamicSharedMemorySize, APPLY_SMEM);
    cudaFuncSetAttribute(mma_kernel, cudaFuncAttributeMaxDynamicSharedMemorySize, MMA_SMEM);

    // one fused softmax pass over all four inputs
    softmax_all<<<800, 256>>>(init, weights, emis, trans, o3, o4, o5);

    // P^T tf32 (needs g_P)
    transpose_P<<<dim3(NN / 32, S / 32), dim3(32, 8)>>>();

    // radix-4 power table: 5 serial levels
    power_level<<<3, 256, POW_SMEM>>>(1);      // T^2..T^4
    power_level<<<12, 256, POW_SMEM>>>(4);     // T^5..T^16
    power_level<<<48, 256, POW_SMEM>>>(16);    // T^17..T^64
    power_level<<<192, 256, POW_SMEM>>>(64);   // T^65..T^256
    power_level<<<255, 256, POW_SMEM>>>(256);  // T^257..T^511

    // batched apply: p_t = p0 * T^t, fused o3 + g_pR (t=1..511)
    apply_powers<<<511, 256, APPLY_SMEM>>>(o3);

    // persistent tf32 GEMM + log epilogue (outputs 1, 2)
    mma_kernel<<<128, 256, MMA_SMEM>>>(o1, o2);
}

// round 11
// speedup vs baseline: 1.1612x; 1.1612x over previous
#include <cuda_runtime.h>
#include <cstdint>

#define S 128
#define C 32
#define NN 4096
#define T 512

extern __shared__ char dyn_smem[];

// ---------------- scratch ----------------
__device__ __align__(256) float g_P[S * NN];      // exp(log_softmax(emission)) [S,N]
__device__ __align__(256) float g_wexp[T * C];    // exp(log_softmax(weights))
__device__ __align__(256) float g_pR[T * C * S];  // p_t, tf32-rounded [T*C, S]
__device__ __align__(256) float g_PTR[NN * S];    // P^T tf32-rounded [n, s]
__device__ __align__(256) float g_Tlvl[5][S * S]; // T^(4^k), tf32-rounded

// ---------------- helpers ----------------
__device__ __forceinline__ uint32_t smem_u32(const void* p) {
    uint32_t a;
    asm("{ .reg .u64 t; cvta.to.shared.u64 t, %1; cvt.u32.u64 %0, t; }" : "=r"(a) : "l"(p));
    return a;
}
__device__ __forceinline__ void cp_async16(uint32_t dst, const void* src) {
    asm volatile("cp.async.cg.shared.global [%0], [%1], 16;" :: "r"(dst), "l"(src));
}
#define CP_COMMIT() asm volatile("cp.async.commit_group;" ::: "memory")
#define CP_WAIT(n)  asm volatile("cp.async.wait_group %0;" :: "n"(n) : "memory")

__device__ __forceinline__ float to_tf32(float x) {
    uint32_t u;
    asm("cvt.rna.tf32.f32 %0, %1;" : "=r"(u) : "f"(x));
    return __uint_as_float(u);
}
__device__ __forceinline__ void mma_tf32(float* d, const uint32_t* a, const uint32_t* b) {
    asm volatile(
        "mma.sync.aligned.m16n8k8.row.col.f32.tf32.tf32.f32 "
        "{%0,%1,%2,%3},{%4,%5,%6,%7},{%8,%9},{%0,%1,%2,%3};"
        : "+f"(d[0]), "+f"(d[1]), "+f"(d[2]), "+f"(d[3])
        : "r"(a[0]), "r"(a[1]), "r"(a[2]), "r"(a[3]), "r"(b[0]), "r"(b[1]));
}
__device__ __forceinline__ float warpRedMax(float v) {
#pragma unroll
    for (int o = 16; o > 0; o >>= 1) v = fmaxf(v, __shfl_xor_sync(0xffffffffu, v, o));
    return v;
}
__device__ __forceinline__ float warpRedSum(float v) {
#pragma unroll
    for (int o = 16; o > 0; o >>= 1) v += __shfl_xor_sync(0xffffffffu, v, o);
    return v;
}

// ---------------- fused log_softmax over all 4 inputs ----------------
// blocks [0,128): emission -> o4 + g_P
// blocks [128,640): weights -> o5 + g_wexp
// blocks [640,672): init -> o3 (t=0) + g_pR (rounded)
// blocks [672,800): trans -> g_Tlvl[0] (rounded)
__global__ void softmax_all(const float* __restrict__ init, const float* __restrict__ weights,
                            const float* __restrict__ emis, const float* __restrict__ trans,
                            float* __restrict__ o3, float* __restrict__ o4, float* __restrict__ o5) {
    int b = blockIdx.x;
    const float* src;
    float* dlog = nullptr;
    float* dexp;
    bool rnd = false;
    int ncols;
    if (b < 128) {
        int row = b;
        src = emis + (size_t)row * NN;  ncols = NN;
        dlog = o4 + (size_t)row * NN;   dexp = g_P + (size_t)row * NN;
    } else if (b < 640) {
        int row = b - 128;
        src = weights + (size_t)row * C;  ncols = C;
        dlog = o5 + (size_t)row * C;      dexp = g_wexp + (size_t)row * C;
    } else if (b < 672) {
        int row = b - 640;
        src = init + (size_t)row * S;  ncols = S;
        dlog = o3 + (size_t)row * S;   dexp = g_pR + (size_t)row * S;
        rnd = true;
    } else {
        int row = b - 672;
        src = trans + (size_t)row * S;  ncols = S;
        dexp = g_Tlvl[0] + (size_t)row * S;   // T^1
        rnd = true;
    }

    int tid = threadIdx.x, lane = tid & 31, wid = tid >> 5;
    __shared__ float red[8];

    float m = -3.4e38f;
    for (int i = tid; i < ncols; i += blockDim.x) m = fmaxf(m, src[i]);
    m = warpRedMax(m);
    if (lane == 0) red[wid] = m;
    __syncthreads();
    if (wid == 0) {
        float v = (lane < 8) ? red[lane] : -3.4e38f;
        v = warpRedMax(v);
        if (lane == 0) red[0] = v;
    }
    __syncthreads();
    m = red[0];
    __syncthreads();

    float s = 0.f;
    for (int i = tid; i < ncols; i += blockDim.x) s += __expf(src[i] - m);
    s = warpRedSum(s);
    if (lane == 0) red[wid] = s;
    __syncthreads();
    if (wid == 0) {
        float v = (lane < 8) ? red[lane] : 0.f;
        v = warpRedSum(v);
        if (lane == 0) red[0] = v;
    }
    __syncthreads();
    float lse = m + __logf(red[0]);

    for (int i = tid; i < ncols; i += blockDim.x) {
        float v = src[i] - lse;
        if (dlog) dlog[i] = v;
        float e = __expf(v);
        dexp[i] = rnd ? to_tf32(e) : e;
    }
}

// ---------------- radix-4 doubling on p ----------------
// Level stride L (lvl index into g_Tlvl). nP = min(3L, 512-L) p-blocks:
//   block b < nP: t = L + b; m = t/L (1..3); j = t%L;
//   X = p_j; repeat m: X = X * T^L; write g_pR[t] (rounded) + o3 logs.
// block b == nP (only if L < 256): T^{4L} = ((T^L)^2)^2 -> g_Tlvl[lvl+1].
static constexpr int PW = 136;
static constexpr int MAT_W = 128 * PW;
static constexpr int EXP_SMEM = 2 * MAT_W * 4;   // 139264

__global__ __launch_bounds__(256, 1) void expand4(int L, int lvl, float* __restrict__ o3) {
    float* sm0 = reinterpret_cast<float*>(dyn_smem);
    float* Ts = sm0;                      // 128 x PW
    int tid = threadIdx.x, lane = tid & 31, wid = tid >> 5;
    int b = blockIdx.x;
    int nP = min(3 * L, 512 - L);

    // load T^L
    const float4* gT = reinterpret_cast<const float4*>(g_Tlvl[lvl]);
    for (int i = tid; i < 4096; i += 256) {
        int row = i >> 5, c = i & 31;
        *reinterpret_cast<float4*>(Ts + row * PW + c * 4) = gT[i];
    }

    if (b < nP) {
        // ---- p-chain block ----
        float* X0 = sm0 + MAT_W;              // 32 x PW
        float* X1 = X0 + 32 * PW;
        int t = L + b;
        int m = t / L;
        int j = t - m * L;

        const float4* gp = reinterpret_cast<const float4*>(g_pR + (size_t)j * C * S);
        for (int i = tid; i < 1024; i += 256) {
            int row = i >> 5, c = i & 31;
            *reinterpret_cast<float4*>(X0 + row * PW + c * 4) = gp[i];
        }
        __syncthreads();

        int wm = wid & 1, wn = wid >> 1;      // rows 16*wm, cols 32*wn
        float* src = X0;
        float* dst = X1;
        for (int it = 0; it < m; it++) {
            float acc[4][4];
#pragma unroll
            for (int nt = 0; nt < 4; nt++)
#pragma unroll
                for (int e = 0; e < 4; e++) acc[nt][e] = 0.f;

#pragma unroll
            for (int kt = 0; kt < 16; kt++) {
                int r = wm * 16 + (lane >> 2), k = kt * 8 + (lane & 3);
                uint32_t a[4];
                a[0] = __float_as_uint(src[r * PW + k]);
                a[1] = __float_as_uint(src[(r + 8) * PW + k]);
                a[2] = __float_as_uint(src[r * PW + k + 4]);
                a[3] = __float_as_uint(src[(r + 8) * PW + k + 4]);
#pragma unroll
                for (int nt = 0; nt < 4; nt++) {
                    int n = wn * 32 + nt * 8 + (lane >> 2);
                    uint32_t bf[2];
                    bf[0] = __float_as_uint(Ts[k * PW + n]);
                    bf[1] = __float_as_uint(Ts[(k + 4) * PW + n]);
                    mma_tf32(acc[nt], a, bf);
                }
            }
            int r = wm * 16 + (lane >> 2), c2 = (lane & 3) * 2;
#pragma unroll
            for (int nt = 0; nt < 4; nt++) {
                int col = wn * 32 + nt * 8 + c2;
                dst[r * PW + col]           = to_tf32(acc[nt][0]);
                dst[r * PW + col + 1]       = to_tf32(acc[nt][1]);
                dst[(r + 8) * PW + col]     = to_tf32(acc[nt][2]);
                dst[(r + 8) * PW + col + 1] = to_tf32(acc[nt][3]);
            }
            __syncthreads();
            float* tmp = src; src = dst; dst = tmp;
        }

        // write g_pR[t] + o3 logs
        float4* gout = reinterpret_cast<float4*>(g_pR + (size_t)t * C * S);
        float* o3out = o3 + (size_t)t * C * S;
        for (int i = tid; i < 1024; i += 256) {
            int row = i >> 5, c = i & 31;
            float4 v = *reinterpret_cast<float4*>(src + row * PW + c * 4);
            gout[i] = v;
            int idx = row * S + c * 4;
            o3out[idx]     = __logf(v.x);
            o3out[idx + 1] = __logf(v.y);
            o3out[idx + 2] = __logf(v.z);
            o3out[idx + 3] = __logf(v.w);
        }
    } else {
        // ---- T-squaring block: T^{4L} = ((T^L)^2)^2 ----
        float* Ys = sm0 + MAT_W;              // 128 x PW
        __syncthreads();
        float* cur = Ts;
        float* dst = Ys;
#pragma unroll
        for (int sq = 0; sq < 2; sq++) {
            float acc[16][4];
#pragma unroll
            for (int nt = 0; nt < 16; nt++)
#pragma unroll
                for (int e = 0; e < 4; e++) acc[nt][e] = 0.f;

#pragma unroll
            for (int kt = 0; kt < 16; kt++) {
                int r = wid * 16 + (lane >> 2), k = kt * 8 + (lane & 3);
                uint32_t a[4];
                a[0] = __float_as_uint(cur[r * PW + k]);
                a[1] = __float_as_uint(cur[(r + 8) * PW + k]);
                a[2] = __float_as_uint(cur[r * PW + k + 4]);
                a[3] = __float_as_uint(cur[(r + 8) * PW + k + 4]);
#pragma unroll
                for (int nt = 0; nt < 16; nt++) {
                    int n = nt * 8 + (lane >> 2);
                    uint32_t bf[2];
                    bf[0] = __float_as_uint(cur[k * PW + n]);
                    bf[1] = __float_as_uint(cur[(k + 4) * PW + n]);
                    mma_tf32(acc[nt], a, bf);
                }
            }
            __syncthreads();   // all reads of cur done before any overwrite next round
            int r = wid * 16 + (lane >> 2), c2 = (lane & 3) * 2;
#pragma unroll
            for (int nt = 0; nt < 16; nt++) {
                int col = nt * 8 + c2;
                dst[r * PW + col]           = to_tf32(acc[nt][0]);
                dst[r * PW + col + 1]       = to_tf32(acc[nt][1]);
                dst[(r + 8) * PW + col]     = to_tf32(acc[nt][2]);
                dst[(r + 8) * PW + col + 1] = to_tf32(acc[nt][3]);
            }
            __syncthreads();
            float* tmp = cur; cur = dst; dst = tmp;
        }
        // result in cur (= Ts after two swaps)
        float4* gout = reinterpret_cast<float4*>(g_Tlvl[lvl + 1]);
        for (int i = tid; i < 4096; i += 256) {
            int row = i >> 5, c = i & 31;
            gout[i] = *reinterpret_cast<float4*>(cur + row * PW + c * 4);
        }
    }
}

// ---------------- transpose P [S,N] -> PTR tf32-rounded [N,S] ----------------
__global__ void transpose_P() {
    __shared__ float ts[32][33];
    int n0 = blockIdx.x * 32, s0 = blockIdx.y * 32;
    int tx = threadIdx.x, ty = threadIdx.y;   // (32, 8)
#pragma unroll
    for (int r = 0; r < 4; r++)
        ts[ty + r * 8][tx] = g_P[(size_t)(s0 + ty + r * 8) * NN + n0 + tx];
    __syncthreads();
#pragma unroll
    for (int r = 0; r < 4; r++) {
        int nloc = ty + r * 8;
        g_PTR[(size_t)(n0 + nloc) * S + s0 + tx] = to_tf32(ts[tx][nloc]);
    }
}

// ---------------- persistent tf32 GEMM + log epilogue (proven) ----------------
static constexpr int A_PW = 132;
static constexpr int A_BYTES = 128 * A_PW * 4;     // 67584
static constexpr int B_PW = 68;
static constexpr int B_CHUNK = 128 * B_PW * 4;     // 34816
static constexpr int MMA_SMEM = A_BYTES + 3 * B_CHUNK;  // 172032

__global__ __launch_bounds__(256, 1)
void mma_kernel(float* __restrict__ o1, float* __restrict__ o2) {
    char* sm = dyn_smem;
    uint32_t smb = smem_u32(sm);
    int tid = threadIdx.x, lane = tid & 31, wid = tid >> 5;
    int quad = blockIdx.x;

    const uint4* srcA = reinterpret_cast<const uint4*>(g_pR) + (size_t)quad * 128 * 32;
#pragma unroll
    for (int j = 0; j < 16; j++) {
        int i = tid + j * 256;
        int row = i >> 5, c = i & 31;
        cp_async16(smb + row * (A_PW * 4) + c * 16, srcA + row * 32 + c);
    }
    CP_COMMIT();

    auto issueB = [&](int chunk) {
        int tile = chunk >> 1, half = chunk & 1;
        const uint4* srcB = reinterpret_cast<const uint4*>(g_PTR)
                            + (size_t)tile * 128 * 32 + half * 16;
        uint32_t base = smb + A_BYTES + (chunk % 3) * B_CHUNK;
#pragma unroll
        for (int j = 0; j < 8; j++) {
            int i = tid + j * 256;
            int row = i >> 4, c = i & 15;
            cp_async16(base + row * (B_PW * 4) + c * 16, srcB + row * 32 + c);
        }
    };
    issueB(0); CP_COMMIT();
    issueB(1); CP_COMMIT();
    issueB(2); CP_COMMIT();

    int mrow = (wid & 3) * 32 + (lane >> 2);
    int nrowBase = (wid >> 2) * 64 + (lane >> 2);
    int kt = lane & 3;
    int t = quad * 4 + (wid & 3);
    int r0 = lane >> 2, cq = lane & 3;
    float wlane = g_wexp[t * C + lane];
    float wr0  = __shfl_sync(0xffffffffu, wlane, r0);
    float wr0b = __shfl_sync(0xffffffffu, wlane, r0 + 8);
    float wr1  = __shfl_sync(0xffffffffu, wlane, 16 + r0);
    float wr1b = __shfl_sync(0xffffffffu, wlane, 16 + r0 + 8);

    const uint32_t* As = reinterpret_cast<const uint32_t*>(sm);
    float acc[2][8][4];

    for (int chunk = 0; chunk < 64; chunk++) {
        int tile = chunk >> 1, half = chunk & 1;
        CP_WAIT(2);
        __syncthreads();
        const uint32_t* Bs =
            reinterpret_cast<const uint32_t*>(sm + A_BYTES + (chunk % 3) * B_CHUNK);

        if (half == 0) {
#pragma unroll
            for (int mt = 0; mt < 2; mt++)
#pragma unroll
                for (int nt = 0; nt < 8; nt++)
#pragma unroll
                    for (int e = 0; e < 4; e++) acc[mt][nt][e] = 0.f;
        }

#pragma unroll
        for (int step = 0; step < 8; step++) {
            int k0 = half * 64 + step * 8 + kt;
            uint32_t a[2][4];
#pragma unroll
            for (int mt = 0; mt < 2; mt++) {
                int r = mrow + mt * 16;
                a[mt][0] = As[r * A_PW + k0];
                a[mt][1] = As[(r + 8) * A_PW + k0];
                a[mt][2] = As[r * A_PW + k0 + 4];
                a[mt][3] = As[(r + 8) * A_PW + k0 + 4];
            }
#pragma unroll
            for (int nt = 0; nt < 8; nt++) {
                int n = nrowBase + nt * 8;
                uint32_t bf[2];
                bf[0] = Bs[n * B_PW + step * 8 + kt];
                bf[1] = Bs[n * B_PW + step * 8 + kt + 4];
#pragma unroll
                for (int mt = 0; mt < 2; mt++) mma_tf32(acc[mt][nt], a[mt], bf);
            }
        }
        __syncthreads();
        if (chunk + 3 < 64) issueB(chunk + 3);
        CP_COMMIT();

        if (half == 1) {
            int nb = tile * 128;
            int nbL = (wid >> 2) * 64;
#pragma unroll
            for (int nt = 0; nt < 8; nt++) {
                int ncol = nb + nbL + nt * 8 + cq * 2;
                float v0, v1;
                {
                    float2 s0 = make_float2(__logf(acc[0][nt][0]), __logf(acc[0][nt][1]));
                    float2 s1 = make_float2(__logf(acc[0][nt][2]), __logf(acc[0][nt][3]));
                    *reinterpret_cast<float2*>(&o2[((size_t)(t * C + r0)) * NN + ncol]) = s0;
                    *reinterpret_cast<float2*>(&o2[((size_t)(t * C + r0 + 8)) * NN + ncol]) = s1;
                    v0 = acc[0][nt][0] * wr0 + acc[0][nt][2] * wr0b;
                    v1 = acc[0][nt][1] * wr0 + acc[0][nt][3] * wr0b;
                }
                {
                    float2 s0 = make_float2(__logf(acc[1][nt][0]), __logf(acc[1][nt][1]));
                    float2 s1 = make_float2(__logf(acc[1][nt][2]), __logf(acc[1][nt][3]));
                    *reinterpret_cast<float2*>(&o2[((size_t)(t * C + 16 + r0)) * NN + ncol]) = s0;
                    *reinterpret_cast<float2*>(&o2[((size_t)(t * C + 24 + r0)) * NN + ncol]) = s1;
                    v0 += acc[1][nt][0] * wr1 + acc[1][nt][2] * wr1b;
                    v1 += acc[1][nt][1] * wr1 + acc[1][nt][3] * wr1b;
                }
#pragma unroll
                for (int o = 4; o < 32; o <<= 1) {
                    v0 += __shfl_xor_sync(0xffffffffu, v0, o);
                    v1 += __shfl_xor_sync(0xffffffffu, v1, o);
                }
                if (lane < 4) {
                    int n = nb + nbL + nt * 8 + lane * 2;
                    *reinterpret_cast<float2*>(&o1[(size_t)t * NN + n]) =
                        make_float2(__logf(v0), __logf(v1));
                }
            }
        }
    }
}

// ---------------- launch ----------------
extern "C" void kernel_launch(void* const* d_in, const int* in_sizes, int n_in,
                              void* d_out, int out_size) {
    (void)in_sizes; (void)n_in; (void)out_size;
    const float* init    = (const float*)d_in[0];   // [32,128]
    const float* weights = (const float*)d_in[1];   // [512,32]
    const float* emis    = (const float*)d_in[2];   // [128,4096]
    const float* trans   = (const float*)d_in[3];   // [128,128]

    float* out = (float*)d_out;
    float* o1 = out;                       // [512,4096]
    float* o2 = o1 + (size_t)T * NN;       // [512,32,4096]
    float* o3 = o2 + (size_t)T * C * NN;   // [512,32,128]
    float* o4 = o3 + (size_t)T * C * S;    // [128,4096]
    float* o5 = o4 + (size_t)S * NN;       // [512,32]

    cudaFuncSetAttribute(expand4, cudaFuncAttributeMaxDynamicSharedMemorySize, EXP_SMEM);
    cudaFuncSetAttribute(mma_kernel, cudaFuncAttributeMaxDynamicSharedMemorySize, MMA_SMEM);

    // one fused softmax pass over all four inputs
    softmax_all<<<800, 256>>>(init, weights, emis, trans, o3, o4, o5);

    // P^T tf32 (needs g_P)
    transpose_P<<<dim3(NN / 32, S / 32), dim3(32, 8)>>>();

    // radix-4 doubling on p: 5 serial levels (each also squares T twice)
    expand4<<<4, 256, EXP_SMEM>>>(1, 0, o3);      // t=1..3,  T^4
    expand4<<<13, 256, EXP_SMEM>>>(4, 1, o3);     // t=4..15, T^16
    expand4<<<49, 256, EXP_SMEM>>>(16, 2, o3);    // t=16..63, T^64
    expand4<<<193, 256, EXP_SMEM>>>(64, 3, o3);   // t=64..255, T^256
    expand4<<<256, 256, EXP_SMEM>>>(256, 4, o3);  // t=256..511

    // persistent tf32 GEMM + log epilogue (outputs 1, 2)
    mma_kernel<<<128, 256, MMA_SMEM>>>(o1, o2);
}

// round 12
// speedup vs baseline: 1.2362x; 1.0645x over previous
#include <cuda_runtime.h>
#include <cstdint>

#define S 128
#define C 32
#define NN 4096
#define T 512

extern __shared__ char dyn_smem[];

// ---------------- scratch ----------------
__device__ __align__(256) float g_wexp[T * C];    // exp(log_softmax(weights))
__device__ __align__(256) float g_pR[T * C * S];  // p_t, tf32-rounded [T*C, S]
__device__ __align__(256) float g_PTR[NN * S];    // P^T tf32-rounded [n, s]
__device__ __align__(256) float g_Tlvl[5][S * S]; // T^(4^k), tf32-rounded
__device__ unsigned g_bcount = 0;                 // grid-barrier counter (self-resetting)
__device__ volatile unsigned g_bsense = 0;        // grid-barrier sense (even flips/run)

// ---------------- helpers ----------------
__device__ __forceinline__ uint32_t smem_u32(const void* p) {
    uint32_t a;
    asm("{ .reg .u64 t; cvta.to.shared.u64 t, %1; cvt.u32.u64 %0, t; }" : "=r"(a) : "l"(p));
    return a;
}
__device__ __forceinline__ void cp_async16(uint32_t dst, const void* src) {
    asm volatile("cp.async.cg.shared.global [%0], [%1], 16;" :: "r"(dst), "l"(src));
}
#define CP_COMMIT() asm volatile("cp.async.commit_group;" ::: "memory")
#define CP_WAIT(n)  asm volatile("cp.async.wait_group %0;" :: "n"(n) : "memory")

__device__ __forceinline__ float to_tf32(float x) {
    uint32_t u;
    asm("cvt.rna.tf32.f32 %0, %1;" : "=r"(u) : "f"(x));
    return __uint_as_float(u);
}
__device__ __forceinline__ void mma_tf32(float* d, const uint32_t* a, const uint32_t* b) {
    asm volatile(
        "mma.sync.aligned.m16n8k8.row.col.f32.tf32.tf32.f32 "
        "{%0,%1,%2,%3},{%4,%5,%6,%7},{%8,%9},{%0,%1,%2,%3};"
        : "+f"(d[0]), "+f"(d[1]), "+f"(d[2]), "+f"(d[3])
        : "r"(a[0]), "r"(a[1]), "r"(a[2]), "r"(a[3]), "r"(b[0]), "r"(b[1]));
}
__device__ __forceinline__ float warpRedMax(float v) {
#pragma unroll
    for (int o = 16; o > 0; o >>= 1) v = fmaxf(v, __shfl_xor_sync(0xffffffffu, v, o));
    return v;
}
__device__ __forceinline__ float warpRedSum(float v) {
#pragma unroll
    for (int o = 16; o > 0; o >>= 1) v += __shfl_xor_sync(0xffffffffu, v, o);
    return v;
}

// ---------------- fused log_softmax over all 4 inputs (+transpose) ----------
// blocks [0,128): emission -> o4 + g_PTR (transposed, tf32)
// blocks [128,640): weights -> o5 + g_wexp
// blocks [640,672): init -> o3 (t=0) + g_pR (rounded)
// blocks [672,800): trans -> g_Tlvl[0] (rounded)
__global__ void softmax_all(const float* __restrict__ init, const float* __restrict__ weights,
                            const float* __restrict__ emis, const float* __restrict__ trans,
                            float* __restrict__ o3, float* __restrict__ o4, float* __restrict__ o5) {
    int b = blockIdx.x;
    const float* src;
    float* dlog = nullptr;
    float* dexp = nullptr;
    bool rnd = false, transp = false;
    int ncols, rowIdx = 0;
    if (b < 128) {
        rowIdx = b;
        src = emis + (size_t)rowIdx * NN;  ncols = NN;
        dlog = o4 + (size_t)rowIdx * NN;   transp = true;
    } else if (b < 640) {
        int row = b - 128;
        src = weights + (size_t)row * C;  ncols = C;
        dlog = o5 + (size_t)row * C;      dexp = g_wexp + (size_t)row * C;
    } else if (b < 672) {
        int row = b - 640;
        src = init + (size_t)row * S;  ncols = S;
        dlog = o3 + (size_t)row * S;   dexp = g_pR + (size_t)row * S;
        rnd = true;
    } else {
        int row = b - 672;
        src = trans + (size_t)row * S;  ncols = S;
        dexp = g_Tlvl[0] + (size_t)row * S;   // T^1
        rnd = true;
    }

    int tid = threadIdx.x, lane = tid & 31, wid = tid >> 5;
    __shared__ float red[8];

    float m = -3.4e38f;
    for (int i = tid; i < ncols; i += blockDim.x) m = fmaxf(m, src[i]);
    m = warpRedMax(m);
    if (lane == 0) red[wid] = m;
    __syncthreads();
    if (wid == 0) {
        float v = (lane < 8) ? red[lane] : -3.4e38f;
        v = warpRedMax(v);
        if (lane == 0) red[0] = v;
    }
    __syncthreads();
    m = red[0];
    __syncthreads();

    float s = 0.f;
    for (int i = tid; i < ncols; i += blockDim.x) s += __expf(src[i] - m);
    s = warpRedSum(s);
    if (lane == 0) red[wid] = s;
    __syncthreads();
    if (wid == 0) {
        float v = (lane < 8) ? red[lane] : 0.f;
        v = warpRedSum(v);
        if (lane == 0) red[0] = v;
    }
    __syncthreads();
    float lse = m + __logf(red[0]);

    for (int i = tid; i < ncols; i += blockDim.x) {
        float v = src[i] - lse;
        if (dlog) dlog[i] = v;
        float e = __expf(v);
        if (transp) {
            g_PTR[(size_t)i * S + rowIdx] = to_tf32(e);   // transposed write
        } else {
            dexp[i] = rnd ? to_tf32(e) : e;
        }
    }
}

// ---------------- single persistent radix-4 doubling kernel ----------------
// 5 levels (L = 1,4,16,64,256) with grid-wide barriers between them.
// Per level: tasks 0..nP-1 are p-chains (t = L+task, m = t/L chained GEMMs),
// task nP (if lvl<4) squares T^L twice -> g_Tlvl[lvl+1].
static constexpr int PW = 136;
static constexpr int MAT_W = 128 * PW;
static constexpr int EXP_SMEM = 2 * MAT_W * 4;   // 139264
static constexpr int EXP_GRID = 128;             // <= SM count: all CTAs co-resident

__global__ __launch_bounds__(256, 1) void expand_fused(float* __restrict__ o3) {
    float* sm0 = reinterpret_cast<float*>(dyn_smem);
    float* Ts = sm0;            // T^L (128 x PW)
    float* W2 = sm0 + MAT_W;    // work buffer (128 x PW)
    int tid = threadIdx.x, lane = tid & 31, wid = tid >> 5;
    int bid = blockIdx.x;
    const int G = EXP_GRID;
    unsigned lsense = 0;

#pragma unroll 1
    for (int lvl = 0; lvl < 5; lvl++) {
        int L = 1 << (2 * lvl);
        // load T^L
        const float4* gT = reinterpret_cast<const float4*>(g_Tlvl[lvl]);
        for (int i = tid; i < 4096; i += 256) {
            int row = i >> 5, c = i & 31;
            *reinterpret_cast<float4*>(Ts + row * PW + c * 4) = gT[i];
        }
        __syncthreads();

        int nP = min(3 * L, 512 - L);
        int nTask = nP + (lvl < 4 ? 1 : 0);
#pragma unroll 1
        for (int task = bid; task < nTask; task += G) {
            if (task < nP) {
                // ---- p-chain: p_t = p_j * (T^L)^m ----
                float* X0 = W2;
                float* X1 = W2 + 32 * PW;
                int t = L + task;
                int m = t / L;
                int j = t - m * L;

                const float4* gp = reinterpret_cast<const float4*>(g_pR + (size_t)j * C * S);
                for (int i = tid; i < 1024; i += 256) {
                    int row = i >> 5, c = i & 31;
                    *reinterpret_cast<float4*>(X0 + row * PW + c * 4) = gp[i];
                }
                __syncthreads();

                int wm = wid & 1, wn = wid >> 1;
                float* srcp = X0;
                float* dstp = X1;
#pragma unroll 1
                for (int it = 0; it < m; it++) {
                    float acc[4][4];
#pragma unroll
                    for (int nt = 0; nt < 4; nt++)
#pragma unroll
                        for (int e = 0; e < 4; e++) acc[nt][e] = 0.f;

#pragma unroll
                    for (int kt = 0; kt < 16; kt++) {
                        int r = wm * 16 + (lane >> 2), k = kt * 8 + (lane & 3);
                        uint32_t a[4];
                        a[0] = __float_as_uint(srcp[r * PW + k]);
                        a[1] = __float_as_uint(srcp[(r + 8) * PW + k]);
                        a[2] = __float_as_uint(srcp[r * PW + k + 4]);
                        a[3] = __float_as_uint(srcp[(r + 8) * PW + k + 4]);
#pragma unroll
                        for (int nt = 0; nt < 4; nt++) {
                            int n = wn * 32 + nt * 8 + (lane >> 2);
                            uint32_t bf[2];
                            bf[0] = __float_as_uint(Ts[k * PW + n]);
                            bf[1] = __float_as_uint(Ts[(k + 4) * PW + n]);
                            mma_tf32(acc[nt], a, bf);
                        }
                    }
                    int r = wm * 16 + (lane >> 2), c2 = (lane & 3) * 2;
#pragma unroll
                    for (int nt = 0; nt < 4; nt++) {
                        int col = wn * 32 + nt * 8 + c2;
                        dstp[r * PW + col]           = to_tf32(acc[nt][0]);
                        dstp[r * PW + col + 1]       = to_tf32(acc[nt][1]);
                        dstp[(r + 8) * PW + col]     = to_tf32(acc[nt][2]);
                        dstp[(r + 8) * PW + col + 1] = to_tf32(acc[nt][3]);
                    }
                    __syncthreads();
                    float* tmp = srcp; srcp = dstp; dstp = tmp;
                }

                // write g_pR[t] + o3 logs
                float4* gout = reinterpret_cast<float4*>(g_pR + (size_t)t * C * S);
                float* o3out = o3 + (size_t)t * C * S;
                for (int i = tid; i < 1024; i += 256) {
                    int row = i >> 5, c = i & 31;
                    float4 v = *reinterpret_cast<float4*>(srcp + row * PW + c * 4);
                    gout[i] = v;
                    int idx = row * S + c * 4;
                    o3out[idx]     = __logf(v.x);
                    o3out[idx + 1] = __logf(v.y);
                    o3out[idx + 2] = __logf(v.z);
                    o3out[idx + 3] = __logf(v.w);
                }
                __syncthreads();   // protect W2 before next task
            } else {
                // ---- T-squaring: T^{4L} = ((T^L)^2)^2 (always this CTA's last task) ----
                float* cur = Ts;
                float* dst = W2;
                __syncthreads();
#pragma unroll
                for (int sq = 0; sq < 2; sq++) {
                    float acc[16][4];
#pragma unroll
                    for (int nt = 0; nt < 16; nt++)
#pragma unroll
                        for (int e = 0; e < 4; e++) acc[nt][e] = 0.f;

#pragma unroll
                    for (int kt = 0; kt < 16; kt++) {
                        int r = wid * 16 + (lane >> 2), k = kt * 8 + (lane & 3);
                        uint32_t a[4];
                        a[0] = __float_as_uint(cur[r * PW + k]);
                        a[1] = __float_as_uint(cur[(r + 8) * PW + k]);
                        a[2] = __float_as_uint(cur[r * PW + k + 4]);
                        a[3] = __float_as_uint(cur[(r + 8) * PW + k + 4]);
#pragma unroll
                        for (int nt = 0; nt < 16; nt++) {
                            int n = nt * 8 + (lane >> 2);
                            uint32_t bf[2];
                            bf[0] = __float_as_uint(cur[k * PW + n]);
                            bf[1] = __float_as_uint(cur[(k + 4) * PW + n]);
                            mma_tf32(acc[nt], a, bf);
                        }
                    }
                    __syncthreads();
                    int r = wid * 16 + (lane >> 2), c2 = (lane & 3) * 2;
#pragma unroll
                    for (int nt = 0; nt < 16; nt++) {
                        int col = nt * 8 + c2;
                        dst[r * PW + col]           = to_tf32(acc[nt][0]);
                        dst[r * PW + col + 1]       = to_tf32(acc[nt][1]);
                        dst[(r + 8) * PW + col]     = to_tf32(acc[nt][2]);
                        dst[(r + 8) * PW + col + 1] = to_tf32(acc[nt][3]);
                    }
                    __syncthreads();
                    float* tmp = cur; cur = dst; dst = tmp;
                }
                float4* gout = reinterpret_cast<float4*>(g_Tlvl[lvl + 1]);
                for (int i = tid; i < 4096; i += 256) {
                    int row = i >> 5, c = i & 31;
                    gout[i] = *reinterpret_cast<float4*>(cur + row * PW + c * 4);
                }
            }
        }

        // grid-wide barrier between levels (4 flips/run: sense returns to 0)
        if (lvl < 4) {
            __threadfence();
            __syncthreads();
            if (tid == 0) {
                unsigned ns = lsense ^ 1u;
                unsigned pre = atomicAdd(&g_bcount, 1u);
                if (pre == (unsigned)G - 1u) {
                    atomicExch(&g_bcount, 0u);
                    __threadfence();
                    g_bsense = ns;
                } else {
                    while (g_bsense != ns) { }
                }
            }
            __syncthreads();
            lsense ^= 1u;
        }
    }
}

// ---------------- persistent tf32 GEMM + log epilogue (proven) ----------------
static constexpr int A_PW = 132;
static constexpr int A_BYTES = 128 * A_PW * 4;     // 67584
static constexpr int B_PW = 68;
static constexpr int B_CHUNK = 128 * B_PW * 4;     // 34816
static constexpr int MMA_SMEM = A_BYTES + 3 * B_CHUNK;  // 172032

__global__ __launch_bounds__(256, 1)
void mma_kernel(float* __restrict__ o1, float* __restrict__ o2) {
    char* sm = dyn_smem;
    uint32_t smb = smem_u32(sm);
    int tid = threadIdx.x, lane = tid & 31, wid = tid >> 5;
    int quad = blockIdx.x;

    const uint4* srcA = reinterpret_cast<const uint4*>(g_pR) + (size_t)quad * 128 * 32;
#pragma unroll
    for (int j = 0; j < 16; j++) {
        int i = tid + j * 256;
        int row = i >> 5, c = i & 31;
        cp_async16(smb + row * (A_PW * 4) + c * 16, srcA + row * 32 + c);
    }
    CP_COMMIT();

    auto issueB = [&](int chunk) {
        int tile = chunk >> 1, half = chunk & 1;
        const uint4* srcB = reinterpret_cast<const uint4*>(g_PTR)
                            + (size_t)tile * 128 * 32 + half * 16;
        uint32_t base = smb + A_BYTES + (chunk % 3) * B_CHUNK;
#pragma unroll
        for (int j = 0; j < 8; j++) {
            int i = tid + j * 256;
            int row = i >> 4, c = i & 15;
            cp_async16(base + row * (B_PW * 4) + c * 16, srcB + row * 32 + c);
        }
    };
    issueB(0); CP_COMMIT();
    issueB(1); CP_COMMIT();
    issueB(2); CP_COMMIT();

    int mrow = (wid & 3) * 32 + (lane >> 2);
    int nrowBase = (wid >> 2) * 64 + (lane >> 2);
    int kt = lane & 3;
    int t = quad * 4 + (wid & 3);
    int r0 = lane >> 2, cq = lane & 3;
    float wlane = g_wexp[t * C + lane];
    float wr0  = __shfl_sync(0xffffffffu, wlane, r0);
    float wr0b = __shfl_sync(0xffffffffu, wlane, r0 + 8);
    float wr1  = __shfl_sync(0xffffffffu, wlane, 16 + r0);
    float wr1b = __shfl_sync(0xffffffffu, wlane, 16 + r0 + 8);

    const uint32_t* As = reinterpret_cast<const uint32_t*>(sm);
    float acc[2][8][4];

    for (int chunk = 0; chunk < 64; chunk++) {
        int tile = chunk >> 1, half = chunk & 1;
        CP_WAIT(2);
        __syncthreads();
        const uint32_t* Bs =
            reinterpret_cast<const uint32_t*>(sm + A_BYTES + (chunk % 3) * B_CHUNK);

        if (half == 0) {
#pragma unroll
            for (int mt = 0; mt < 2; mt++)
#pragma unroll
                for (int nt = 0; nt < 8; nt++)
#pragma unroll
                    for (int e = 0; e < 4; e++) acc[mt][nt][e] = 0.f;
        }

#pragma unroll
        for (int step = 0; step < 8; step++) {
            int k0 = half * 64 + step * 8 + kt;
            uint32_t a[2][4];
#pragma unroll
            for (int mt = 0; mt < 2; mt++) {
                int r = mrow + mt * 16;
                a[mt][0] = As[r * A_PW + k0];
                a[mt][1] = As[(r + 8) * A_PW + k0];
                a[mt][2] = As[r * A_PW + k0 + 4];
                a[mt][3] = As[(r + 8) * A_PW + k0 + 4];
            }
#pragma unroll
            for (int nt = 0; nt < 8; nt++) {
                int n = nrowBase + nt * 8;
                uint32_t bf[2];
                bf[0] = Bs[n * B_PW + step * 8 + kt];
                bf[1] = Bs[n * B_PW + step * 8 + kt + 4];
#pragma unroll
                for (int mt = 0; mt < 2; mt++) mma_tf32(acc[mt][nt], a[mt], bf);
            }
        }
        __syncthreads();
        if (chunk + 3 < 64) issueB(chunk + 3);
        CP_COMMIT();

        if (half == 1) {
            int nb = tile * 128;
            int nbL = (wid >> 2) * 64;
#pragma unroll
            for (int nt = 0; nt < 8; nt++) {
                int ncol = nb + nbL + nt * 8 + cq * 2;
                float v0, v1;
                {
                    float2 s0 = make_float2(__logf(acc[0][nt][0]), __logf(acc[0][nt][1]));
                    float2 s1 = make_float2(__logf(acc[0][nt][2]), __logf(acc[0][nt][3]));
                    *reinterpret_cast<float2*>(&o2[((size_t)(t * C + r0)) * NN + ncol]) = s0;
                    *reinterpret_cast<float2*>(&o2[((size_t)(t * C + r0 + 8)) * NN + ncol]) = s1;
                    v0 = acc[0][nt][0] * wr0 + acc[0][nt][2] * wr0b;
                    v1 = acc[0][nt][1] * wr0 + acc[0][nt][3] * wr0b;
                }
                {
                    float2 s0 = make_float2(__logf(acc[1][nt][0]), __logf(acc[1][nt][1]));
                    float2 s1 = make_float2(__logf(acc[1][nt][2]), __logf(acc[1][nt][3]));
                    *reinterpret_cast<float2*>(&o2[((size_t)(t * C + 16 + r0)) * NN + ncol]) = s0;
                    *reinterpret_cast<float2*>(&o2[((size_t)(t * C + 24 + r0)) * NN + ncol]) = s1;
                    v0 += acc[1][nt][0] * wr1 + acc[1][nt][2] * wr1b;
                    v1 += acc[1][nt][1] * wr1 + acc[1][nt][3] * wr1b;
                }
#pragma unroll
                for (int o = 4; o < 32; o <<= 1) {
                    v0 += __shfl_xor_sync(0xffffffffu, v0, o);
                    v1 += __shfl_xor_sync(0xffffffffu, v1, o);
                }
                if (lane < 4) {
                    int n = nb + nbL + nt * 8 + lane * 2;
                    *reinterpret_cast<float2*>(&o1[(size_t)t * NN + n]) =
                        make_float2(__logf(v0), __logf(v1));
                }
            }
        }
    }
}

// ---------------- launch ----------------
extern "C" void kernel_launch(void* const* d_in, const int* in_sizes, int n_in,
                              void* d_out, int out_size) {
    (void)in_sizes; (void)n_in; (void)out_size;
    const float* init    = (const float*)d_in[0];   // [32,128]
    const float* weights = (const float*)d_in[1];   // [512,32]
    const float* emis    = (const float*)d_in[2];   // [128,4096]
    const float* trans   = (const float*)d_in[3];   // [128,128]

    float* out = (float*)d_out;
    float* o1 = out;                       // [512,4096]
    float* o2 = o1 + (size_t)T * NN;       // [512,32,4096]
    float* o3 = o2 + (size_t)T * C * NN;   // [512,32,128]
    float* o4 = o3 + (size_t)T * C * S;    // [128,4096]
    float* o5 = o4 + (size_t)S * NN;       // [512,32]

    cudaFuncSetAttribute(expand_fused, cudaFuncAttributeMaxDynamicSharedMemorySize, EXP_SMEM);
    cudaFuncSetAttribute(mma_kernel, cudaFuncAttributeMaxDynamicSharedMemorySize, MMA_SMEM);

    // 1) fused softmax over all inputs + P transpose
    softmax_all<<<800, 256>>>(init, weights, emis, trans, o3, o4, o5);

    // 2) all 5 doubling levels in ONE persistent kernel (grid barriers inside)
    expand_fused<<<EXP_GRID, 256, EXP_SMEM>>>(o3);

    // 3) persistent tf32 GEMM + log epilogue (outputs 1, 2)
    mma_kernel<<<128, 256, MMA_SMEM>>>(o1, o2);
}